// round 5
// baseline (speedup 1.0000x reference)
#include <cuda_runtime.h>

// Problem constants
#define AA   128      // A (nodes)
#define SPN  1024     // S*P
#define FF   128      // features
#define HH   4        // heads
#define DD   128      // hidden per head
#define NNW  512      // H*D
#define RR   131072   // SP*A rows

// Scratch (static device globals — allocation-rule safe)
__device__ __align__(16) float g_gr[(size_t)RR * NNW];   // g_r: [sp][a][h*128+d]  (268 MB)
__device__ __align__(16) float g_sl[RR * HH];
__device__ __align__(16) float g_sr[RR * HH];
__device__ __align__(16) float g_ul[FF * HH];
__device__ __align__(16) float g_ur[FF * HH];

// ---- packed f32x2 helpers (Blackwell FFMA2 path; only reachable via PTX) ----
__device__ __forceinline__ unsigned long long pk2(float lo, float hi) {
    unsigned long long r;
    asm("mov.b64 %0, {%1,%2};" : "=l"(r) : "f"(lo), "f"(hi));
    return r;
}
__device__ __forceinline__ void ffma2(unsigned long long& d,
                                      unsigned long long a, unsigned long long b) {
    asm("fma.rn.f32x2 %0, %1, %2, %0;" : "+l"(d) : "l"(a), "l"(b));
}
__device__ __forceinline__ float2 upk2(unsigned long long v) {
    float2 r;
    asm("mov.b64 {%0,%1}, %2;" : "=f"(r.x), "=f"(r.y) : "l"(v));
    return r;
}

// ============================================================
// K1: u_l[f,h] = sum_d W_l[f, h*D+d] * w_attn[d]
//     u_r[f,h] = sum_d W_r[f, h*D+d] * w_attn[D+d]
// ============================================================
__global__ void k_u(const float* __restrict__ Wl, const float* __restrict__ Wr,
                    const float* __restrict__ wa) {
    __shared__ float w[2 * DD];
    int t = threadIdx.x;               // 512 threads
    if (t < 2 * DD) w[t] = wa[t];
    __syncthreads();
    int f = t >> 2, hh = t & 3;
    const float* pl = Wl + (size_t)f * NNW + hh * DD;
    const float* pr = Wr + (size_t)f * NNW + hh * DD;
    float sl = 0.f, sr = 0.f;
#pragma unroll 4
    for (int d = 0; d < DD; d++) {
        sl = fmaf(pl[d], w[d], sl);
        sr = fmaf(pr[d], w[DD + d], sr);
    }
    g_ul[f * HH + hh] = sl;
    g_ur[f * HH + hh] = sr;
}

// ============================================================
// K2: s_l[sp,a,h] = sum_f h[a,sp,f] * u_l[f,h]  (and s_r)
//     one warp per row (sp,a)
// ============================================================
__global__ void __launch_bounds__(256) k_s(const float* __restrict__ h) {
    __shared__ float ul[FF * HH], ur[FF * HH];
    int t = threadIdx.x;
    for (int q = t; q < FF * HH; q += 256) { ul[q] = g_ul[q]; ur[q] = g_ur[q]; }
    __syncthreads();
    int warp = t >> 5, lane = t & 31;
    int rid = blockIdx.x * 8 + warp;        // rid = sp*128 + a
    int sp = rid >> 7, a = rid & 127;
    const float* hr = h + ((size_t)a * SPN + sp) * FF;
    float hv[4];
#pragma unroll
    for (int u = 0; u < 4; u++) hv[u] = hr[lane + 32 * u];
    float accl[4] = {0, 0, 0, 0}, accr[4] = {0, 0, 0, 0};
#pragma unroll
    for (int u = 0; u < 4; u++) {
        int f = lane + 32 * u;
#pragma unroll
        for (int hh = 0; hh < 4; hh++) {
            accl[hh] = fmaf(hv[u], ul[f * 4 + hh], accl[hh]);
            accr[hh] = fmaf(hv[u], ur[f * 4 + hh], accr[hh]);
        }
    }
#pragma unroll
    for (int hh = 0; hh < 4; hh++) {
        for (int o = 16; o; o >>= 1) {
            accl[hh] += __shfl_xor_sync(0xffffffffu, accl[hh], o);
            accr[hh] += __shfl_xor_sync(0xffffffffu, accr[hh], o);
        }
    }
    if (lane == 0) {
        *(float4*)&g_sl[rid * 4] = make_float4(accl[0], accl[1], accl[2], accl[3]);
        *(float4*)&g_sr[rid * 4] = make_float4(accr[0], accr[1], accr[2], accr[3]);
    }
}

// ============================================================
// K3: g_r = h_ @ W_r : per block (sp, nb) computes 128x128 tile, K=128
//     A row a  -> h[(a*SP + sp)*128 + k],  B -> W_r[k*512 + nb*128 + n]
// ============================================================
__global__ void __launch_bounds__(256) k_gemm_gr(const float* __restrict__ h,
                                                 const float* __restrict__ Wr) {
    __shared__ float As[16][132];   // [k][m], padded
    __shared__ float Bs[16][128];   // [k][n]
    int sp = blockIdx.x, nb = blockIdx.y;
    int tid = threadIdx.x;
    int ty = tid >> 4, tx = tid & 15;
    int row0 = ty * 8, col0 = tx * 8;

    unsigned long long acc2[8][4];
#pragma unroll
    for (int i = 0; i < 8; i++)
#pragma unroll
        for (int j = 0; j < 4; j++) acc2[i][j] = 0ull;

    for (int k0 = 0; k0 < FF; k0 += 16) {
#pragma unroll
        for (int p = 0; p < 2; p++) {
            int r = (tid >> 2) + p * 64;
            int c4 = (tid & 3) * 4;
            float4 v = *(const float4*)&h[((size_t)r * SPN + sp) * FF + k0 + c4];
            As[c4 + 0][r] = v.x; As[c4 + 1][r] = v.y;
            As[c4 + 2][r] = v.z; As[c4 + 3][r] = v.w;
        }
#pragma unroll
        for (int p = 0; p < 2; p++) {
            int r = (tid >> 5) + p * 8;
            int c4 = (tid & 31) * 4;
            *(float4*)&Bs[r][c4] = *(const float4*)&Wr[(size_t)(k0 + r) * NNW + nb * 128 + c4];
        }
        __syncthreads();
#pragma unroll
        for (int kk = 0; kk < 16; kk++) {
            float av[8], bv[8];
            *(float4*)&av[0] = *(const float4*)&As[kk][row0];
            *(float4*)&av[4] = *(const float4*)&As[kk][row0 + 4];
            *(float4*)&bv[0] = *(const float4*)&Bs[kk][col0];
            *(float4*)&bv[4] = *(const float4*)&Bs[kk][col0 + 4];
            unsigned long long b2[4];
#pragma unroll
            for (int jp = 0; jp < 4; jp++) b2[jp] = pk2(bv[2 * jp], bv[2 * jp + 1]);
#pragma unroll
            for (int ii = 0; ii < 8; ii++) {
                unsigned long long a2 = pk2(av[ii], av[ii]);
#pragma unroll
                for (int jp = 0; jp < 4; jp++) ffma2(acc2[ii][jp], a2, b2[jp]);
            }
        }
        __syncthreads();
    }
#pragma unroll
    for (int ii = 0; ii < 8; ii++) {
        int r = row0 + ii;
        float out[8];
#pragma unroll
        for (int jp = 0; jp < 4; jp++) {
            float2 f = upk2(acc2[ii][jp]);
            out[2 * jp] = f.x; out[2 * jp + 1] = f.y;
        }
        float* dst = &g_gr[((size_t)sp * 128 + r) * NNW + nb * 128 + col0];
        *(float4*)dst = *(float4*)&out[0];
        *(float4*)(dst + 4) = *(float4*)&out[4];
    }
}

// ============================================================
// K4a: attention scores + softmax, one warp per (sp, i) row.
//      e[i,j,h] = leaky_relu(s_r[sp,i,h] + s_l[sp,j,h]), diag->-inf,
//      softmax over j; write a[s,p,i,j,h] coalesced as float4 (the 4 heads).
// ============================================================
__global__ void __launch_bounds__(256) k_soft(float* __restrict__ out2) {
    int t = threadIdx.x;
    int warp = t >> 5, lane = t & 31;
    int pair = blockIdx.x * 8 + warp;       // sp*128 + i
    int sp = pair >> 7, i = pair & 127;
    float4 sri = *(const float4*)&g_sr[pair * 4];
    float e[4][4];
#pragma unroll
    for (int u = 0; u < 4; u++) {
        int j = lane + 32 * u;
        float4 slj = *(const float4*)&g_sl[(sp * 128 + j) * 4];
        float v[4] = {sri.x + slj.x, sri.y + slj.y, sri.z + slj.z, sri.w + slj.w};
#pragma unroll
        for (int hh = 0; hh < 4; hh++) {
            float x = v[hh];
            x = (x >= 0.f) ? x : 0.2f * x;
            e[u][hh] = (j == i) ? -3.0e38f : x;
        }
    }
#pragma unroll
    for (int hh = 0; hh < 4; hh++) {
        float m = fmaxf(fmaxf(e[0][hh], e[1][hh]), fmaxf(e[2][hh], e[3][hh]));
        for (int o = 16; o; o >>= 1) m = fmaxf(m, __shfl_xor_sync(0xffffffffu, m, o));
        float s = 0.f;
#pragma unroll
        for (int u = 0; u < 4; u++) {
            int j = lane + 32 * u;
            float p = (j == i) ? 0.f : __expf(e[u][hh] - m);
            e[u][hh] = p;
            s += p;
        }
        for (int o = 16; o; o >>= 1) s += __shfl_xor_sync(0xffffffffu, s, o);
        float inv = 1.0f / s;
#pragma unroll
        for (int u = 0; u < 4; u++) e[u][hh] *= inv;
    }
    float* base = out2 + (size_t)sp * 65536 + (size_t)i * 512;
#pragma unroll
    for (int u = 0; u < 4; u++) {
        int j = lane + 32 * u;
        *(float4*)&base[j * 4] = make_float4(e[u][0], e[u][1], e[u][2], e[u][3]);
    }
}

// ============================================================
// K4b: attn_res[sp,i,d] = 0.25 * sum_k a2[sp,i,k] * g_r[sp,k,d]   (K = j*4+h = 512)
//      one block per sp: (128x512)@(512x128); output in (A,S,P,D) layout.
// ============================================================
__global__ void __launch_bounds__(256) k_av(const float* __restrict__ a2,
                                            float* __restrict__ out1) {
    __shared__ float As[16][132];
    __shared__ float Bs[16][128];
    int sp = blockIdx.x;
    int tid = threadIdx.x;
    int ty = tid >> 4, tx = tid & 15;
    int row0 = ty * 8, col0 = tx * 8;
    const float* Ab = a2 + (size_t)sp * 65536;
    const float* Bb = g_gr + (size_t)sp * 65536;

    unsigned long long acc2[8][4];
#pragma unroll
    for (int i = 0; i < 8; i++)
#pragma unroll
        for (int j = 0; j < 4; j++) acc2[i][j] = 0ull;

    for (int k0 = 0; k0 < 512; k0 += 16) {
#pragma unroll
        for (int p = 0; p < 2; p++) {
            int r = (tid >> 2) + p * 64;
            int c4 = (tid & 3) * 4;
            float4 v = *(const float4*)&Ab[(size_t)r * 512 + k0 + c4];
            As[c4 + 0][r] = v.x; As[c4 + 1][r] = v.y;
            As[c4 + 2][r] = v.z; As[c4 + 3][r] = v.w;
        }
#pragma unroll
        for (int p = 0; p < 2; p++) {
            int r = (tid >> 5) + p * 8;
            int c4 = (tid & 31) * 4;
            *(float4*)&Bs[r][c4] = *(const float4*)&Bb[(size_t)(k0 + r) * 128 + c4];
        }
        __syncthreads();
#pragma unroll
        for (int kk = 0; kk < 16; kk++) {
            float av[8], bv[8];
            *(float4*)&av[0] = *(const float4*)&As[kk][row0];
            *(float4*)&av[4] = *(const float4*)&As[kk][row0 + 4];
            *(float4*)&bv[0] = *(const float4*)&Bs[kk][col0];
            *(float4*)&bv[4] = *(const float4*)&Bs[kk][col0 + 4];
            unsigned long long b2[4];
#pragma unroll
            for (int jp = 0; jp < 4; jp++) b2[jp] = pk2(bv[2 * jp], bv[2 * jp + 1]);
#pragma unroll
            for (int ii = 0; ii < 8; ii++) {
                unsigned long long a2r = pk2(av[ii], av[ii]);
#pragma unroll
                for (int jp = 0; jp < 4; jp++) ffma2(acc2[ii][jp], a2r, b2[jp]);
            }
        }
        __syncthreads();
    }
#pragma unroll
    for (int ii = 0; ii < 8; ii++) {
        int i = row0 + ii;
        float out[8];
#pragma unroll
        for (int jp = 0; jp < 4; jp++) {
            float2 f = upk2(acc2[ii][jp]);
            out[2 * jp] = f.x * 0.25f; out[2 * jp + 1] = f.y * 0.25f;
        }
        float* dst = out1 + ((size_t)i * SPN + sp) * 128 + col0;
        *(float4*)dst = *(float4*)&out[0];
        *(float4*)(dst + 4) = *(float4*)&out[4];
    }
}

// ============================================================
extern "C" void kernel_launch(void* const* d_in, const int* in_sizes, int n_in,
                              void* d_out, int out_size) {
    const float* h  = (const float*)d_in[0];
    const float* Wl = (const float*)d_in[1];
    const float* Wr = (const float*)d_in[2];
    const float* wa = (const float*)d_in[3];

    float* out1 = (float*)d_out;                          // attn_res: A*S*P*D
    float* out2 = out1 + (size_t)AA * SPN * DD;           // a: S*P*A*A*H

    k_u<<<1, 512>>>(Wl, Wr, wa);
    k_s<<<RR / 8, 256>>>(h);
    k_gemm_gr<<<dim3(SPN, 4), 256>>>(h, Wr);
    k_soft<<<RR / 8, 256>>>(out2);
    k_av<<<SPN, 256>>>(out2, out1);
}

// round 8
// speedup vs baseline: 1.2894x; 1.2894x over previous
#include <cuda_runtime.h>
#include <cuda_fp16.h>
#include <cstdint>

// Problem constants
#define AA   128
#define SPN  1024
#define FF   128
#define HH   4
#define DD   128
#define NNW  512
#define RR   131072

// ------------------------------------------------------------------
// Scratch (static device globals — allocation-rule safe)
// ------------------------------------------------------------------
__device__ __align__(16) unsigned int g_hs[(size_t)RR * FF];            // h split: [sp][a][f] (f16 hi|lo<<16) 67MB
__device__ __align__(16) unsigned int g_wt[NNW * FF];                   // W_r^T split: [n_g][f]
__device__ __align__(16) unsigned int g_gt[(size_t)SPN * 2 * NNW * 64]; // gT planes: [sp][plane][n][a-pair] 268MB
__device__ __align__(16) __half      g_af[(size_t)HH * SPN * AA * AA];  // a fp16: [h][sp][i][j] 134MB
__device__ __align__(16) float g_sl[RR * HH];
__device__ __align__(16) float g_sr[RR * HH];
__device__ __align__(16) float g_ul[FF * HH];
__device__ __align__(16) float g_ur[FF * HH];

// ------------------------------------------------------------------
// PTX helpers (sm_80-level only: ldmatrix + mma.sync — valid on plain sm_103)
// ------------------------------------------------------------------
__device__ __forceinline__ uint32_t smem_u32(const void* p) {
    uint32_t a;
    asm("{ .reg .u64 t; cvta.to.shared.u64 t, %1; cvt.u32.u64 %0, t; }" : "=r"(a) : "l"(p));
    return a;
}
__device__ __forceinline__ void ldsm4(uint32_t* r, uint32_t addr) {
    asm volatile("ldmatrix.sync.aligned.m8n8.x4.shared.b16 {%0,%1,%2,%3}, [%4];"
                 : "=r"(r[0]), "=r"(r[1]), "=r"(r[2]), "=r"(r[3]) : "r"(addr));
}
__device__ __forceinline__ void ldsm2(uint32_t* r, uint32_t addr) {
    asm volatile("ldmatrix.sync.aligned.m8n8.x2.shared.b16 {%0,%1}, [%2];"
                 : "=r"(r[0]), "=r"(r[1]) : "r"(addr));
}
__device__ __forceinline__ void mma16816(float* c, const uint32_t* a, const uint32_t* b) {
    asm volatile("mma.sync.aligned.m16n8k16.row.col.f32.f16.f16.f32 "
                 "{%0,%1,%2,%3}, {%4,%5,%6,%7}, {%8,%9}, {%0,%1,%2,%3};"
                 : "+f"(c[0]), "+f"(c[1]), "+f"(c[2]), "+f"(c[3])
                 : "r"(a[0]), "r"(a[1]), "r"(a[2]), "r"(a[3]), "r"(b[0]), "r"(b[1]));
}
__device__ __forceinline__ uint32_t prmt(uint32_t a, uint32_t b, uint32_t sel) {
    uint32_t d;
    asm("prmt.b32 %0, %1, %2, %3;" : "=r"(d) : "r"(a), "r"(b), "r"(sel));
    return d;
}
// fp32 -> packed (f16 hi in low 16 | f16 lo in high 16)
__device__ __forceinline__ unsigned int split_f16(float x) {
    __half hi = __float2half_rn(x);
    float hf = __half2float(hi);
    __half lo = __float2half_rn(x - hf);
    return (unsigned int)__half_as_ushort(hi) | ((unsigned int)__half_as_ushort(lo) << 16);
}

// ============================================================
// K1: fold w_attn into W_l / W_r per head
// ============================================================
__global__ void k_u(const float* __restrict__ Wl, const float* __restrict__ Wr,
                    const float* __restrict__ wa) {
    __shared__ float w[2 * DD];
    int t = threadIdx.x;               // 512 threads
    if (t < 2 * DD) w[t] = wa[t];
    __syncthreads();
    int f = t >> 2, hh = t & 3;
    const float* pl = Wl + (size_t)f * NNW + hh * DD;
    const float* pr = Wr + (size_t)f * NNW + hh * DD;
    float sl = 0.f, sr = 0.f;
#pragma unroll 4
    for (int d = 0; d < DD; d++) {
        sl = fmaf(pl[d], w[d], sl);
        sr = fmaf(pr[d], w[DD + d], sr);
    }
    g_ul[f * HH + hh] = sl;
    g_ur[f * HH + hh] = sr;
}

// ============================================================
// K2: s_l / s_r  (one warp per row) — exact fp32
// ============================================================
__global__ void __launch_bounds__(256) k_s(const float* __restrict__ h) {
    __shared__ float ul[FF * HH], ur[FF * HH];
    int t = threadIdx.x;
    for (int q = t; q < FF * HH; q += 256) { ul[q] = g_ul[q]; ur[q] = g_ur[q]; }
    __syncthreads();
    int warp = t >> 5, lane = t & 31;
    int rid = blockIdx.x * 8 + warp;
    int sp = rid >> 7, a = rid & 127;
    const float* hr = h + ((size_t)a * SPN + sp) * FF;
    float hv[4];
#pragma unroll
    for (int u = 0; u < 4; u++) hv[u] = hr[lane + 32 * u];
    float accl[4] = {0, 0, 0, 0}, accr[4] = {0, 0, 0, 0};
#pragma unroll
    for (int u = 0; u < 4; u++) {
        int f = lane + 32 * u;
#pragma unroll
        for (int hh = 0; hh < 4; hh++) {
            accl[hh] = fmaf(hv[u], ul[f * 4 + hh], accl[hh]);
            accr[hh] = fmaf(hv[u], ur[f * 4 + hh], accr[hh]);
        }
    }
#pragma unroll
    for (int hh = 0; hh < 4; hh++) {
        for (int o = 16; o; o >>= 1) {
            accl[hh] += __shfl_xor_sync(0xffffffffu, accl[hh], o);
            accr[hh] += __shfl_xor_sync(0xffffffffu, accr[hh], o);
        }
    }
    if (lane == 0) {
        *(float4*)&g_sl[rid * 4] = make_float4(accl[0], accl[1], accl[2], accl[3]);
        *(float4*)&g_sr[rid * 4] = make_float4(accr[0], accr[1], accr[2], accr[3]);
    }
}

// ============================================================
// K3a: split h into fp16 hi/lo pairs, transposed to [sp][a][f]
// ============================================================
__global__ void __launch_bounds__(256) k_split_h(const float* __restrict__ h) {
    unsigned int e = blockIdx.x * 256 + threadIdx.x;   // < RR*FF = 2^24
    int f = e & 127, a = (e >> 7) & 127, sp = e >> 14;
    float v = h[((size_t)a * SPN + sp) * FF + f];
    g_hs[e] = split_f16(v);
}

// K3b: split + transpose W_r : g_wt[n][f] = split(W_r[f][n])
__global__ void __launch_bounds__(256) k_split_w(const float* __restrict__ Wr) {
    int t = blockIdx.x * 256 + threadIdx.x;            // < NNW*FF = 65536
    int f = t & 127, n = t >> 7;
    g_wt[t] = split_f16(Wr[(size_t)f * NNW + n]);
}

// ============================================================
// K4: GEMM1 — gT[sp][n][a] = sum_f Wt[n][f] * h[sp][a][f]
//     mma.sync fp16 hi/lo, 3 combos (err ~2^-22).
//     CTA = (nb, sp): 128(n) x 128(a), K=128 in two 64-chunks.
//     Output: two u32-pair planes (hi, lo) in g_gt.
// ============================================================
// SMEM: per chunk, 4 planes of [128 rows][72 halves] (stride 144B, ldmatrix conflict-free)
#define G1_PLANE 18432                    // 128*72*2
#define G1_AHI   0
#define G1_ALO   18432
#define G1_BHI   36864
#define G1_BLO   55296
#define G1_SIZE  73728

__global__ void __launch_bounds__(256) k_g1() {
    extern __shared__ char smem[];
    uint32_t sb = smem_u32(smem);
    int tid = threadIdx.x;
    int lane = tid & 31, wid = tid >> 5;
    int wm = wid & 1, wn = wid >> 1;      // warp tile: 64(m=n_g) x 32(n=a)
    int nb = blockIdx.x, sp = blockIdx.y;

    float acc[4][4][4];
#pragma unroll
    for (int i = 0; i < 4; i++)
#pragma unroll
        for (int j = 0; j < 4; j++)
#pragma unroll
            for (int q = 0; q < 4; q++) acc[i][j][q] = 0.f;

    for (int kc = 0; kc < 2; kc++) {
        // fill: Wt rows (A) and h rows (B), de-interleave hi/lo via PRMT
        for (int idx = tid; idx < 4096; idx += 256) {
            int row = idx >> 5, c2 = idx & 31;          // c2: pair of f within chunk
            uint2 vw = ((const uint2*)g_wt)[(size_t)(nb * 128 + row) * 64 + kc * 32 + c2];
            uint2 vh = ((const uint2*)g_hs)[((size_t)sp * 128 + row) * 64 + kc * 32 + c2];
            uint32_t off = row * 144 + c2 * 4;
            *(uint32_t*)(smem + G1_AHI + off) = prmt(vw.x, vw.y, 0x5410);
            *(uint32_t*)(smem + G1_ALO + off) = prmt(vw.x, vw.y, 0x7632);
            *(uint32_t*)(smem + G1_BHI + off) = prmt(vh.x, vh.y, 0x5410);
            *(uint32_t*)(smem + G1_BLO + off) = prmt(vh.x, vh.y, 0x7632);
        }
        __syncthreads();

#pragma unroll
        for (int ks = 0; ks < 4; ks++) {
            int kb = ks * 16;
            // B fragments (a-dim), hi & lo
            uint32_t bh[4][2], bl[4][2];
            int bko = kb + ((lane >> 3) & 1) * 8;
#pragma unroll
            for (int nt = 0; nt < 4; nt++) {
                uint32_t boff = (uint32_t)((wn * 32 + nt * 8 + (lane & 7)) * 72 + bko) * 2;
                ldsm2(bh[nt], sb + G1_BHI + boff);
                ldsm2(bl[nt], sb + G1_BLO + boff);
            }
            int ako = kb + (lane >> 4) * 8;
#pragma unroll
            for (int mt = 0; mt < 4; mt++) {
                uint32_t aoff = (uint32_t)((wm * 64 + mt * 16 + (lane & 15)) * 72 + ako) * 2;
                uint32_t ah[4], al[4];
                ldsm4(ah, sb + G1_AHI + aoff);
                ldsm4(al, sb + G1_ALO + aoff);
#pragma unroll
                for (int nt = 0; nt < 4; nt++) {
                    mma16816(acc[mt][nt], ah, bh[nt]);
                    mma16816(acc[mt][nt], ah, bl[nt]);
                    mma16816(acc[mt][nt], al, bh[nt]);
                }
            }
        }
        __syncthreads();
    }

    // epilogue: split each fp32 to hi/lo halves, store as u32 col-pairs
    size_t baseHi = ((size_t)sp * 2 + 0) * NNW * 64;
    size_t baseLo = ((size_t)sp * 2 + 1) * NNW * 64;
#pragma unroll
    for (int mt = 0; mt < 4; mt++) {
#pragma unroll
        for (int nt = 0; nt < 4; nt++) {
            int gn0 = nb * 128 + wm * 64 + mt * 16 + (lane >> 2);
            int p = wn * 16 + nt * 4 + (lane & 3);
            uint32_t s0 = split_f16(acc[mt][nt][0]);
            uint32_t s1 = split_f16(acc[mt][nt][1]);
            g_gt[baseHi + (size_t)gn0 * 64 + p] = prmt(s0, s1, 0x5410);
            g_gt[baseLo + (size_t)gn0 * 64 + p] = prmt(s0, s1, 0x7632);
            uint32_t s2 = split_f16(acc[mt][nt][2]);
            uint32_t s3 = split_f16(acc[mt][nt][3]);
            g_gt[baseHi + (size_t)(gn0 + 8) * 64 + p] = prmt(s2, s3, 0x5410);
            g_gt[baseLo + (size_t)(gn0 + 8) * 64 + p] = prmt(s2, s3, 0x7632);
        }
    }
}

// ============================================================
// K5: scores + softmax; writes fp32 a to out2 AND fp16 a planes
// ============================================================
__global__ void __launch_bounds__(256) k_soft(float* __restrict__ out2) {
    int t = threadIdx.x;
    int warp = t >> 5, lane = t & 31;
    int pair = blockIdx.x * 8 + warp;
    int sp = pair >> 7, i = pair & 127;
    float4 sri = *(const float4*)&g_sr[pair * 4];
    float e[4][4];
#pragma unroll
    for (int u = 0; u < 4; u++) {
        int j = lane + 32 * u;
        float4 slj = *(const float4*)&g_sl[(sp * 128 + j) * 4];
        float v[4] = {sri.x + slj.x, sri.y + slj.y, sri.z + slj.z, sri.w + slj.w};
#pragma unroll
        for (int hh = 0; hh < 4; hh++) {
            float x = v[hh];
            x = (x >= 0.f) ? x : 0.2f * x;
            e[u][hh] = (j == i) ? -3.0e38f : x;
        }
    }
#pragma unroll
    for (int hh = 0; hh < 4; hh++) {
        float m = fmaxf(fmaxf(e[0][hh], e[1][hh]), fmaxf(e[2][hh], e[3][hh]));
        for (int o = 16; o; o >>= 1) m = fmaxf(m, __shfl_xor_sync(0xffffffffu, m, o));
        float s = 0.f;
#pragma unroll
        for (int u = 0; u < 4; u++) {
            int j = lane + 32 * u;
            float p = (j == i) ? 0.f : __expf(e[u][hh] - m);
            e[u][hh] = p;
            s += p;
        }
        for (int o = 16; o; o >>= 1) s += __shfl_xor_sync(0xffffffffu, s, o);
        float inv = 1.0f / s;
#pragma unroll
        for (int u = 0; u < 4; u++) e[u][hh] *= inv;
    }
    float* base = out2 + (size_t)sp * 65536 + (size_t)i * 512;
#pragma unroll
    for (int u = 0; u < 4; u++) {
        int j = lane + 32 * u;
        *(float4*)&base[j * 4] = make_float4(e[u][0], e[u][1], e[u][2], e[u][3]);
    }
    // fp16 planes [h][sp][i][j]
#pragma unroll
    for (int hh = 0; hh < 4; hh++) {
        __half* ab = g_af + (((size_t)hh * SPN + sp) * 128 + i) * 128;
#pragma unroll
        for (int u = 0; u < 4; u++) ab[lane + 32 * u] = __float2half_rn(e[u][hh]);
    }
}

// ============================================================
// K6: GEMM2 — attn_res[i][d] = 0.25 * sum_{h,j} a_h[i][j] * gT[h*128+d][j]
//     CTA per sp: 128(i) x 128(d), K=512 over 4 head-chunks of 128.
//     A = fp16 a (single plane), B = gT hi/lo → 2 combos.
// ============================================================
// SMEM: A [128][136] halves; Bhi/Blo [128][136] halves (stride 272B)
#define G2_A    0
#define G2_BHI  34816
#define G2_BLO  69632
#define G2_SIZE 104448

__global__ void __launch_bounds__(256) k_g2(float* __restrict__ out1) {
    extern __shared__ char smem[];
    uint32_t sb = smem_u32(smem);
    int tid = threadIdx.x;
    int lane = tid & 31, wid = tid >> 5;
    int wm = wid & 1, wn = wid >> 1;      // warp tile: 64(i) x 32(d)
    int sp = blockIdx.x;

    float acc[4][4][4];
#pragma unroll
    for (int i = 0; i < 4; i++)
#pragma unroll
        for (int j = 0; j < 4; j++)
#pragma unroll
            for (int q = 0; q < 4; q++) acc[i][j][q] = 0.f;

    for (int hh = 0; hh < 4; hh++) {
        // fill A: a plane [i][j] 8192 u32 (contiguous), padded stride 68 u32
        {
            const uint32_t* srcA = (const uint32_t*)(g_af + (((size_t)hh * SPN + sp) * 128) * 128);
            const uint32_t* srcH = g_gt + (((size_t)sp * 2 + 0) * NNW + hh * 128) * 64;
            const uint32_t* srcL = g_gt + (((size_t)sp * 2 + 1) * NNW + hh * 128) * 64;
            for (int idx = tid; idx < 8192; idx += 256) {
                int row = idx >> 6, c = idx & 63;
                uint32_t doff = (uint32_t)(row * 68 + c) * 4;
                *(uint32_t*)(smem + G2_A + doff) = srcA[idx];
                *(uint32_t*)(smem + G2_BHI + doff) = srcH[idx];
                *(uint32_t*)(smem + G2_BLO + doff) = srcL[idx];
            }
        }
        __syncthreads();

#pragma unroll
        for (int ks = 0; ks < 8; ks++) {
            int kb = ks * 16;
            uint32_t bh[4][2], bl[4][2];
            int bko = kb + ((lane >> 3) & 1) * 8;
#pragma unroll
            for (int nt = 0; nt < 4; nt++) {
                uint32_t boff = (uint32_t)((wn * 32 + nt * 8 + (lane & 7)) * 136 + bko) * 2;
                ldsm2(bh[nt], sb + G2_BHI + boff);
                ldsm2(bl[nt], sb + G2_BLO + boff);
            }
            int ako = kb + (lane >> 4) * 8;
#pragma unroll
            for (int mt = 0; mt < 4; mt++) {
                uint32_t aoff = (uint32_t)((wm * 64 + mt * 16 + (lane & 15)) * 136 + ako) * 2;
                uint32_t af[4];
                ldsm4(af, sb + G2_A + aoff);
#pragma unroll
                for (int nt = 0; nt < 4; nt++) {
                    mma16816(acc[mt][nt], af, bh[nt]);
                    mma16816(acc[mt][nt], af, bl[nt]);
                }
            }
        }
        __syncthreads();
    }

    // epilogue: x0.25, output layout (A, S, P, D): out1[(i*SPN + sp)*128 + d]
#pragma unroll
    for (int mt = 0; mt < 4; mt++) {
#pragma unroll
        for (int nt = 0; nt < 4; nt++) {
            int i0 = wm * 64 + mt * 16 + (lane >> 2);
            int d0 = wn * 32 + nt * 8 + (lane & 3) * 2;
            float2 v0 = make_float2(acc[mt][nt][0] * 0.25f, acc[mt][nt][1] * 0.25f);
            float2 v1 = make_float2(acc[mt][nt][2] * 0.25f, acc[mt][nt][3] * 0.25f);
            *(float2*)&out1[((size_t)i0 * SPN + sp) * 128 + d0] = v0;
            *(float2*)&out1[((size_t)(i0 + 8) * SPN + sp) * 128 + d0] = v1;
        }
    }
}

// ============================================================
extern "C" void kernel_launch(void* const* d_in, const int* in_sizes, int n_in,
                              void* d_out, int out_size) {
    const float* h  = (const float*)d_in[0];
    const float* Wl = (const float*)d_in[1];
    const float* Wr = (const float*)d_in[2];
    const float* wa = (const float*)d_in[3];

    float* out1 = (float*)d_out;                 // attn_res: A*S*P*D
    float* out2 = out1 + (size_t)AA * SPN * DD;  // a: S*P*A*A*H

    // Unconditional (no static guards): immediate, idempotent, capture-safe.
    cudaFuncSetAttribute(k_g1, cudaFuncAttributeMaxDynamicSharedMemorySize, G1_SIZE);
    cudaFuncSetAttribute(k_g2, cudaFuncAttributeMaxDynamicSharedMemorySize, G2_SIZE);

    k_u<<<1, 512>>>(Wl, Wr, wa);
    k_s<<<RR / 8, 256>>>(h);
    k_split_h<<<(RR * FF) / 256, 256>>>(h);
    k_split_w<<<(NNW * FF) / 256, 256>>>(Wr);
    k_g1<<<dim3(4, SPN), 256, G1_SIZE>>>();
    k_soft<<<RR / 8, 256>>>(out2);
    k_g2<<<SPN, 256, G2_SIZE>>>(out1);
}

// round 12
// speedup vs baseline: 1.6778x; 1.3013x over previous
#include <cuda_runtime.h>
#include <cuda_fp16.h>
#include <cstdint>

// Problem constants
#define AA   128
#define SPN  1024
#define FF   128
#define HH   4
#define DD   128
#define NNW  512
#define RR   131072

// ------------------------------------------------------------------
// Scratch (static device globals — allocation-rule safe)
// ------------------------------------------------------------------
__device__ __align__(16) unsigned int g_wt[NNW * FF];                 // W_r^T split: [n_g][f] (f16 hi|lo<<16)
__device__ __align__(16) __half      g_gt[(size_t)SPN * NNW * AA];    // gT fp16: [sp][n_g][a]  134MB
__device__ __align__(16) float g_sl[RR * HH];
__device__ __align__(16) float g_sr[RR * HH];
__device__ __align__(16) float g_ul[FF * HH];
__device__ __align__(16) float g_ur[FF * HH];

// ------------------------------------------------------------------
// PTX helpers (sm_80-level: ldmatrix + mma.sync + cp.async — valid on plain sm_103)
// ------------------------------------------------------------------
__device__ __forceinline__ uint32_t smem_u32(const void* p) {
    uint32_t a;
    asm("{ .reg .u64 t; cvta.to.shared.u64 t, %1; cvt.u32.u64 %0, t; }" : "=r"(a) : "l"(p));
    return a;
}
__device__ __forceinline__ void ldsm4(uint32_t* r, uint32_t addr) {
    asm volatile("ldmatrix.sync.aligned.m8n8.x4.shared.b16 {%0,%1,%2,%3}, [%4];"
                 : "=r"(r[0]), "=r"(r[1]), "=r"(r[2]), "=r"(r[3]) : "r"(addr));
}
__device__ __forceinline__ void ldsm2(uint32_t* r, uint32_t addr) {
    asm volatile("ldmatrix.sync.aligned.m8n8.x2.shared.b16 {%0,%1}, [%2];"
                 : "=r"(r[0]), "=r"(r[1]) : "r"(addr));
}
__device__ __forceinline__ void mma16816(float* c, const uint32_t* a, const uint32_t* b) {
    asm volatile("mma.sync.aligned.m16n8k16.row.col.f32.f16.f16.f32 "
                 "{%0,%1,%2,%3}, {%4,%5,%6,%7}, {%8,%9}, {%0,%1,%2,%3};"
                 : "+f"(c[0]), "+f"(c[1]), "+f"(c[2]), "+f"(c[3])
                 : "r"(a[0]), "r"(a[1]), "r"(a[2]), "r"(a[3]), "r"(b[0]), "r"(b[1]));
}
__device__ __forceinline__ uint32_t prmt(uint32_t a, uint32_t b, uint32_t sel) {
    uint32_t d;
    asm("prmt.b32 %0, %1, %2, %3;" : "=r"(d) : "r"(a), "r"(b), "r"(sel));
    return d;
}
__device__ __forceinline__ void cpasync16(uint32_t dst, const void* src) {
    asm volatile("cp.async.cg.shared.global [%0], [%1], 16;" :: "r"(dst), "l"(src));
}
__device__ __forceinline__ void cpcommit() { asm volatile("cp.async.commit_group;"); }
template<int N> __device__ __forceinline__ void cpwait() {
    asm volatile("cp.async.wait_group %0;" :: "n"(N));
}
// __half2 -> u32 bit-cast (portable; __half2_as_uint is absent in this toolchain)
__device__ __forceinline__ uint32_t h2_u32(__half2 v) {
    return *reinterpret_cast<uint32_t*>(&v);
}
// fp32 -> packed (f16 hi in low 16 | f16 lo in high 16)
__device__ __forceinline__ unsigned int split_f16(float x) {
    __half hi = __float2half_rn(x);
    float hf = __half2float(hi);
    __half lo = __float2half_rn(x - hf);
    return (unsigned int)__half_as_ushort(hi) | ((unsigned int)__half_as_ushort(lo) << 16);
}

// ============================================================
// K1: fold w_attn into W_l / W_r per head
// ============================================================
__global__ void k_u(const float* __restrict__ Wl, const float* __restrict__ Wr,
                    const float* __restrict__ wa) {
    __shared__ float w[2 * DD];
    int t = threadIdx.x;               // 512 threads
    if (t < 2 * DD) w[t] = wa[t];
    __syncthreads();
    int f = t >> 2, hh = t & 3;
    const float* pl = Wl + (size_t)f * NNW + hh * DD;
    const float* pr = Wr + (size_t)f * NNW + hh * DD;
    float sl = 0.f, sr = 0.f;
#pragma unroll 4
    for (int d = 0; d < DD; d++) {
        sl = fmaf(pl[d], w[d], sl);
        sr = fmaf(pr[d], w[DD + d], sr);
    }
    g_ul[f * HH + hh] = sl;
    g_ur[f * HH + hh] = sr;
}

// ============================================================
// K2: s_l / s_r  (one warp per row) — exact fp32
// ============================================================
__global__ void __launch_bounds__(256) k_s(const float* __restrict__ h) {
    __shared__ float ul[FF * HH], ur[FF * HH];
    int t = threadIdx.x;
    for (int q = t; q < FF * HH; q += 256) { ul[q] = g_ul[q]; ur[q] = g_ur[q]; }
    __syncthreads();
    int warp = t >> 5, lane = t & 31;
    int rid = blockIdx.x * 8 + warp;
    int sp = rid >> 7, a = rid & 127;
    const float* hr = h + ((size_t)a * SPN + sp) * FF;
    float hv[4];
#pragma unroll
    for (int u = 0; u < 4; u++) hv[u] = hr[lane + 32 * u];
    float accl[4] = {0, 0, 0, 0}, accr[4] = {0, 0, 0, 0};
#pragma unroll
    for (int u = 0; u < 4; u++) {
        int f = lane + 32 * u;
#pragma unroll
        for (int hh = 0; hh < 4; hh++) {
            accl[hh] = fmaf(hv[u], ul[f * 4 + hh], accl[hh]);
            accr[hh] = fmaf(hv[u], ur[f * 4 + hh], accr[hh]);
        }
    }
#pragma unroll
    for (int hh = 0; hh < 4; hh++) {
        for (int o = 16; o; o >>= 1) {
            accl[hh] += __shfl_xor_sync(0xffffffffu, accl[hh], o);
            accr[hh] += __shfl_xor_sync(0xffffffffu, accr[hh], o);
        }
    }
    if (lane == 0) {
        *(float4*)&g_sl[rid * 4] = make_float4(accl[0], accl[1], accl[2], accl[3]);
        *(float4*)&g_sr[rid * 4] = make_float4(accr[0], accr[1], accr[2], accr[3]);
    }
}

// ============================================================
// K3: split + transpose W_r : g_wt[n][f] = split(W_r[f][n])
// ============================================================
__global__ void __launch_bounds__(256) k_split_w(const float* __restrict__ Wr) {
    int t = blockIdx.x * 256 + threadIdx.x;            // < NNW*FF = 65536
    int f = t & 127, n = t >> 7;
    g_wt[t] = split_f16(Wr[(size_t)f * NNW + n]);
}

// ============================================================
// K4: GEMM1 — gT[sp][n][a] = sum_f Wt[n][f] * h[sp][a][f]
//     2-MMA scheme: (Wt_hi + Wt_lo) * h_hi  (err ~2e-4 on g; attn_res only).
//     CTA = (nb, sp): 128(n) x 128(a), full K=128 in SMEM.
//     h loaded fp32 directly (no split scratch); output single fp16 plane.
// ============================================================
// SMEM planes [128 rows][136 halves] (stride 272B, ldmatrix conflict-free)
#define G1_AHI   0
#define G1_ALO   34816
#define G1_BHI   69632
#define G1_SIZE  104448

__global__ void __launch_bounds__(256) k_g1(const float* __restrict__ h) {
    extern __shared__ char smem[];
    uint32_t sb = smem_u32(smem);
    int tid = threadIdx.x;
    int lane = tid & 31, wid = tid >> 5;
    int wm = wid & 1, wn = wid >> 1;      // warp tile: 64(m=n_g) x 32(n=a)
    int nb = blockIdx.x, sp = blockIdx.y;

    // fill A: Wt hi/lo planes (de-interleave pairs via PRMT)
    for (int idx = tid; idx < 8192; idx += 256) {     // 128 rows x 64 uint2
        int row = idx >> 6, c = idx & 63;
        uint2 vw = ((const uint2*)g_wt)[(size_t)(nb * 128 + row) * 64 + c];
        uint32_t off = (uint32_t)(row * 136 + c * 2) * 2;
        *(uint32_t*)(smem + G1_AHI + off) = prmt(vw.x, vw.y, 0x5410);
        *(uint32_t*)(smem + G1_ALO + off) = prmt(vw.x, vw.y, 0x7632);
    }
    // fill B: h fp32 -> fp16 hi only
    for (int idx = tid; idx < 4096; idx += 256) {     // 128 rows x 32 float4
        int row = idx >> 5, c = idx & 31;
        float4 v = *(const float4*)&h[((size_t)row * SPN + sp) * FF + c * 4];
        uint32_t off = (uint32_t)(row * 136 + c * 4) * 2;
        *(uint32_t*)(smem + G1_BHI + off) = h2_u32(__floats2half2_rn(v.x, v.y));
        *(uint32_t*)(smem + G1_BHI + off + 4) = h2_u32(__floats2half2_rn(v.z, v.w));
    }
    __syncthreads();

    float acc[4][4][4];
#pragma unroll
    for (int i = 0; i < 4; i++)
#pragma unroll
        for (int j = 0; j < 4; j++)
#pragma unroll
            for (int q = 0; q < 4; q++) acc[i][j][q] = 0.f;

#pragma unroll
    for (int ks = 0; ks < 8; ks++) {
        int kb = ks * 16;
        uint32_t bh[4][2];
        int bko = kb + ((lane >> 3) & 1) * 8;
#pragma unroll
        for (int nt = 0; nt < 4; nt++) {
            uint32_t boff = (uint32_t)((wn * 32 + nt * 8 + (lane & 7)) * 136 + bko) * 2;
            ldsm2(bh[nt], sb + G1_BHI + boff);
        }
        int ako = kb + (lane >> 4) * 8;
#pragma unroll
        for (int mt = 0; mt < 4; mt++) {
            uint32_t aoff = (uint32_t)((wm * 64 + mt * 16 + (lane & 15)) * 136 + ako) * 2;
            uint32_t ah[4], al[4];
            ldsm4(ah, sb + G1_AHI + aoff);
            ldsm4(al, sb + G1_ALO + aoff);
#pragma unroll
            for (int nt = 0; nt < 4; nt++) {
                mma16816(acc[mt][nt], ah, bh[nt]);
                mma16816(acc[mt][nt], al, bh[nt]);
            }
        }
    }

    // epilogue: fp16 single plane, half2 stores
#pragma unroll
    for (int mt = 0; mt < 4; mt++) {
#pragma unroll
        for (int nt = 0; nt < 4; nt++) {
            int gn0 = nb * 128 + wm * 64 + mt * 16 + (lane >> 2);
            int col = wn * 32 + nt * 8 + (lane & 3) * 2;
            *(__half2*)&g_gt[((size_t)sp * 512 + gn0) * 128 + col] =
                __floats2half2_rn(acc[mt][nt][0], acc[mt][nt][1]);
            *(__half2*)&g_gt[((size_t)sp * 512 + gn0 + 8) * 128 + col] =
                __floats2half2_rn(acc[mt][nt][2], acc[mt][nt][3]);
        }
    }
}

// ============================================================
// K5: fused softmax + AV GEMM, one CTA per sp.
//     Phase 1: scores from s_l/s_r, softmax; exact fp32 'a' -> out2,
//              fp16 copy -> SMEM planes [h][i][j].
//     Phase 2: attn_res[i][d] = 0.25 * sum_{h,j} a_h[i][j]*gT[h*128+d][j]
//              B tiles (g fp16) double-buffered via cp.async.
// ============================================================
#define G2_A     0                        // 4 planes x 128 x 136 halves
#define G2_PLANE 34816
#define G2_B0    139264
#define G2_B1    174080
#define G2_SIZE  208896

// B tile fill: 128 rows x 256B = 16 chunks of 16B per row, padded row stride 272B.
__device__ __forceinline__ void fill_b_tile(uint32_t dbuf, const __half* src, int tid) {
#pragma unroll
    for (int q = 0; q < 8; q++) {
        int idx = tid + q * 256;          // 0..2047
        int r = idx >> 4, c = idx & 15;   // r: 0..127 rows, c: 0..15 16B-chunks
        cpasync16(dbuf + (uint32_t)(r * 272 + c * 16), src + r * 128 + c * 8);
    }
    cpcommit();
}

__global__ void __launch_bounds__(256) k_g2(float* __restrict__ out1,
                                            float* __restrict__ out2) {
    extern __shared__ char smem[];
    uint32_t sb = smem_u32(smem);
    int tid = threadIdx.x;
    int lane = tid & 31, wid = tid >> 5;
    int wm = wid & 1, wn = wid >> 1;      // warp tile: 64(i) x 32(d)
    int sp = blockIdx.x;

    // prefetch head-0 B tile
    fill_b_tile(sb + G2_B0, g_gt + (size_t)sp * 65536, tid);

    // ---- Phase 1: softmax (warp per row, 16 rows per warp) ----
    {
        float4 slj[4];
#pragma unroll
        for (int u = 0; u < 4; u++)
            slj[u] = *(const float4*)&g_sl[(sp * 128 + lane + 32 * u) * 4];

        for (int it = 0; it < 16; it++) {
            int i = it * 8 + wid;
            float4 sri = *(const float4*)&g_sr[(sp * 128 + i) * 4];
            float e[4][4];
#pragma unroll
            for (int u = 0; u < 4; u++) {
                int j = lane + 32 * u;
                float v[4] = {sri.x + slj[u].x, sri.y + slj[u].y,
                              sri.z + slj[u].z, sri.w + slj[u].w};
#pragma unroll
                for (int hh = 0; hh < 4; hh++) {
                    float x = v[hh];
                    x = (x >= 0.f) ? x : 0.2f * x;
                    e[u][hh] = (j == i) ? -3.0e38f : x;
                }
            }
#pragma unroll
            for (int hh = 0; hh < 4; hh++) {
                float m = fmaxf(fmaxf(e[0][hh], e[1][hh]), fmaxf(e[2][hh], e[3][hh]));
                for (int o = 16; o; o >>= 1) m = fmaxf(m, __shfl_xor_sync(0xffffffffu, m, o));
                float s = 0.f;
#pragma unroll
                for (int u = 0; u < 4; u++) {
                    int j = lane + 32 * u;
                    float p = (j == i) ? 0.f : __expf(e[u][hh] - m);
                    e[u][hh] = p;
                    s += p;
                }
                for (int o = 16; o; o >>= 1) s += __shfl_xor_sync(0xffffffffu, s, o);
                float inv = 1.0f / s;
#pragma unroll
                for (int u = 0; u < 4; u++) e[u][hh] *= inv;
            }
            // exact fp32 'a' to output
            float* base = out2 + (size_t)sp * 65536 + (size_t)i * 512;
#pragma unroll
            for (int u = 0; u < 4; u++) {
                int j = lane + 32 * u;
                *(float4*)&base[j * 4] = make_float4(e[u][0], e[u][1], e[u][2], e[u][3]);
            }
            // fp16 copy into SMEM planes
#pragma unroll
            for (int hh = 0; hh < 4; hh++) {
                uint32_t pb = G2_A + hh * G2_PLANE + (uint32_t)(i * 136) * 2;
#pragma unroll
                for (int u = 0; u < 4; u++) {
                    int j = lane + 32 * u;
                    *(__half*)(smem + pb + j * 2) = __float2half_rn(e[u][hh]);
                }
            }
        }
    }
    __syncthreads();

    // ---- Phase 2: AV MMA over 4 heads ----
    float acc[4][4][4];
#pragma unroll
    for (int i = 0; i < 4; i++)
#pragma unroll
        for (int j = 0; j < 4; j++)
#pragma unroll
            for (int q = 0; q < 4; q++) acc[i][j][q] = 0.f;

    for (int hh = 0; hh < 4; hh++) {
        if (hh < 3) {   // prefetch next head into other buffer
            uint32_t dbuf = ((hh + 1) & 1) ? G2_B1 : G2_B0;
            fill_b_tile(sb + dbuf, g_gt + (size_t)sp * 65536 + (hh + 1) * 128 * 128, tid);
            cpwait<1>();
        } else {
            cpwait<0>();
        }
        __syncthreads();

        uint32_t bbuf = (hh & 1) ? G2_B1 : G2_B0;
        uint32_t aplane = G2_A + hh * G2_PLANE;
#pragma unroll
        for (int ks = 0; ks < 8; ks++) {
            int kb = ks * 16;
            uint32_t bh[4][2];
            int bko = kb + ((lane >> 3) & 1) * 8;
#pragma unroll
            for (int nt = 0; nt < 4; nt++) {
                uint32_t boff = (uint32_t)((wn * 32 + nt * 8 + (lane & 7)) * 136 + bko) * 2;
                ldsm2(bh[nt], sb + bbuf + boff);
            }
            int ako = kb + (lane >> 4) * 8;
#pragma unroll
            for (int mt = 0; mt < 4; mt++) {
                uint32_t aoff = (uint32_t)((wm * 64 + mt * 16 + (lane & 15)) * 136 + ako) * 2;
                uint32_t af[4];
                ldsm4(af, sb + aplane + aoff);
#pragma unroll
                for (int nt = 0; nt < 4; nt++) mma16816(acc[mt][nt], af, bh[nt]);
            }
        }
        __syncthreads();   // all warps done with bbuf before it is refilled (hh+2)
    }

    // epilogue: x0.25, output layout (A, S, P, D)
#pragma unroll
    for (int mt = 0; mt < 4; mt++) {
#pragma unroll
        for (int nt = 0; nt < 4; nt++) {
            int i0 = wm * 64 + mt * 16 + (lane >> 2);
            int d0 = wn * 32 + nt * 8 + (lane & 3) * 2;
            float2 v0 = make_float2(acc[mt][nt][0] * 0.25f, acc[mt][nt][1] * 0.25f);
            float2 v1 = make_float2(acc[mt][nt][2] * 0.25f, acc[mt][nt][3] * 0.25f);
            *(float2*)&out1[((size_t)i0 * SPN + sp) * 128 + d0] = v0;
            *(float2*)&out1[((size_t)(i0 + 8) * SPN + sp) * 128 + d0] = v1;
        }
    }
}

// ============================================================
extern "C" void kernel_launch(void* const* d_in, const int* in_sizes, int n_in,
                              void* d_out, int out_size) {
    const float* h  = (const float*)d_in[0];
    const float* Wl = (const float*)d_in[1];
    const float* Wr = (const float*)d_in[2];
    const float* wa = (const float*)d_in[3];

    float* out1 = (float*)d_out;                 // attn_res: A*S*P*D
    float* out2 = out1 + (size_t)AA * SPN * DD;  // a: S*P*A*A*H

    // Unconditional (no static guards): immediate, idempotent, capture-safe.
    cudaFuncSetAttribute(k_g1, cudaFuncAttributeMaxDynamicSharedMemorySize, G1_SIZE);
    cudaFuncSetAttribute(k_g2, cudaFuncAttributeMaxDynamicSharedMemorySize, G2_SIZE);

    k_u<<<1, 512>>>(Wl, Wr, wa);
    k_s<<<RR / 8, 256>>>(h);
    k_split_w<<<(NNW * FF) / 256, 256>>>(Wr);
    k_g1<<<dim3(4, SPN), 256, G1_SIZE>>>(h);
    k_g2<<<SPN, 256, G2_SIZE>>>(out1, out2);
}

// round 13
// speedup vs baseline: 2.0765x; 1.2376x over previous
#include <cuda_runtime.h>
#include <cuda_fp16.h>
#include <cstdint>

// Problem constants
#define AA   128
#define SPN  1024
#define FF   128
#define HH   4
#define DD   128
#define NNW  512
#define RR   131072

// ------------------------------------------------------------------
// Scratch (static device globals — allocation-rule safe)
// ------------------------------------------------------------------
__device__ __align__(16) __half g_wth[NNW * FF];                      // W_r^T fp16: [n_g][f]
__device__ __align__(16) __half g_gt[(size_t)SPN * NNW * AA];         // gT fp16: [sp][n_g][a]  134MB
__device__ __align__(16) float g_sl[RR * HH];
__device__ __align__(16) float g_sr[RR * HH];
__device__ __align__(16) float g_ul[FF * HH];
__device__ __align__(16) float g_ur[FF * HH];

// ------------------------------------------------------------------
// PTX helpers (sm_80-level: ldmatrix + mma.sync + cp.async — valid on plain sm_103)
// ------------------------------------------------------------------
__device__ __forceinline__ uint32_t smem_u32(const void* p) {
    uint32_t a;
    asm("{ .reg .u64 t; cvta.to.shared.u64 t, %1; cvt.u32.u64 %0, t; }" : "=r"(a) : "l"(p));
    return a;
}
__device__ __forceinline__ void ldsm4(uint32_t* r, uint32_t addr) {
    asm volatile("ldmatrix.sync.aligned.m8n8.x4.shared.b16 {%0,%1,%2,%3}, [%4];"
                 : "=r"(r[0]), "=r"(r[1]), "=r"(r[2]), "=r"(r[3]) : "r"(addr));
}
__device__ __forceinline__ void ldsm2(uint32_t* r, uint32_t addr) {
    asm volatile("ldmatrix.sync.aligned.m8n8.x2.shared.b16 {%0,%1}, [%2];"
                 : "=r"(r[0]), "=r"(r[1]) : "r"(addr));
}
__device__ __forceinline__ void mma16816(float* c, const uint32_t* a, const uint32_t* b) {
    asm volatile("mma.sync.aligned.m16n8k16.row.col.f32.f16.f16.f32 "
                 "{%0,%1,%2,%3}, {%4,%5,%6,%7}, {%8,%9}, {%0,%1,%2,%3};"
                 : "+f"(c[0]), "+f"(c[1]), "+f"(c[2]), "+f"(c[3])
                 : "r"(a[0]), "r"(a[1]), "r"(a[2]), "r"(a[3]), "r"(b[0]), "r"(b[1]));
}
__device__ __forceinline__ void cpasync16(uint32_t dst, const void* src) {
    asm volatile("cp.async.cg.shared.global [%0], [%1], 16;" :: "r"(dst), "l"(src));
}
__device__ __forceinline__ void cpcommit() { asm volatile("cp.async.commit_group;"); }
template<int N> __device__ __forceinline__ void cpwait() {
    asm volatile("cp.async.wait_group %0;" :: "n"(N));
}
// __half2 -> u32 bit-cast
__device__ __forceinline__ uint32_t h2_u32(__half2 v) {
    return *reinterpret_cast<uint32_t*>(&v);
}

// ============================================================
// K1: fold w_attn into W_l / W_r per head
// ============================================================
__global__ void k_u(const float* __restrict__ Wl, const float* __restrict__ Wr,
                    const float* __restrict__ wa) {
    __shared__ float w[2 * DD];
    int t = threadIdx.x;               // 512 threads
    if (t < 2 * DD) w[t] = wa[t];
    __syncthreads();
    int f = t >> 2, hh = t & 3;
    const float* pl = Wl + (size_t)f * NNW + hh * DD;
    const float* pr = Wr + (size_t)f * NNW + hh * DD;
    float sl = 0.f, sr = 0.f;
#pragma unroll 4
    for (int d = 0; d < DD; d++) {
        sl = fmaf(pl[d], w[d], sl);
        sr = fmaf(pr[d], w[DD + d], sr);
    }
    g_ul[f * HH + hh] = sl;
    g_ur[f * HH + hh] = sr;
}

// ============================================================
// K2: s_l / s_r  (one warp per row) — exact fp32
// ============================================================
__global__ void __launch_bounds__(256) k_s(const float* __restrict__ h) {
    __shared__ float ul[FF * HH], ur[FF * HH];
    int t = threadIdx.x;
    for (int q = t; q < FF * HH; q += 256) { ul[q] = g_ul[q]; ur[q] = g_ur[q]; }
    __syncthreads();
    int warp = t >> 5, lane = t & 31;
    int rid = blockIdx.x * 8 + warp;
    int sp = rid >> 7, a = rid & 127;
    const float* hr = h + ((size_t)a * SPN + sp) * FF;
    float hv[4];
#pragma unroll
    for (int u = 0; u < 4; u++) hv[u] = hr[lane + 32 * u];
    float accl[4] = {0, 0, 0, 0}, accr[4] = {0, 0, 0, 0};
#pragma unroll
    for (int u = 0; u < 4; u++) {
        int f = lane + 32 * u;
#pragma unroll
        for (int hh = 0; hh < 4; hh++) {
            accl[hh] = fmaf(hv[u], ul[f * 4 + hh], accl[hh]);
            accr[hh] = fmaf(hv[u], ur[f * 4 + hh], accr[hh]);
        }
    }
#pragma unroll
    for (int hh = 0; hh < 4; hh++) {
        for (int o = 16; o; o >>= 1) {
            accl[hh] += __shfl_xor_sync(0xffffffffu, accl[hh], o);
            accr[hh] += __shfl_xor_sync(0xffffffffu, accr[hh], o);
        }
    }
    if (lane == 0) {
        *(float4*)&g_sl[rid * 4] = make_float4(accl[0], accl[1], accl[2], accl[3]);
        *(float4*)&g_sr[rid * 4] = make_float4(accr[0], accr[1], accr[2], accr[3]);
    }
}

// ============================================================
// K3: transpose W_r to fp16: g_wth[n][f] = fp16(W_r[f][n])
// ============================================================
__global__ void __launch_bounds__(256) k_split_w(const float* __restrict__ Wr) {
    int t = blockIdx.x * 256 + threadIdx.x;            // < NNW*FF = 65536
    int f = t & 127, n = t >> 7;
    g_wth[t] = __float2half_rn(Wr[(size_t)f * NNW + n]);
}

// ============================================================
// K4: GEMM1 — gT[sp][n][a] = sum_f Wt[n][f] * h[sp][a][f]
//     1-MMA fp16 (W_hi × h_hi).  CTA = (nb, sp): 128(n) x 128(a), K=128.
//     SMEM 69.6KB -> 3 CTAs/SM (occupancy fix for the R12 latency bound).
// ============================================================
// SMEM planes [128 rows][136 halves] (stride 272B, ldmatrix conflict-free)
#define G1_A     0
#define G1_B     34816
#define G1_SIZE  69632

__global__ void __launch_bounds__(256) k_g1(const float* __restrict__ h) {
    extern __shared__ char smem[];
    uint32_t sb = smem_u32(smem);
    int tid = threadIdx.x;
    int lane = tid & 31, wid = tid >> 5;
    int wm = wid & 1, wn = wid >> 1;      // warp tile: 64(m=n_g) x 32(n=a)
    int nb = blockIdx.x, sp = blockIdx.y;

    // fill A: Wt fp16 rows (contiguous u32 copies)
    for (int idx = tid; idx < 8192; idx += 256) {     // 128 rows x 64 u32
        int row = idx >> 6, c = idx & 63;
        uint32_t v = ((const uint32_t*)g_wth)[(size_t)(nb * 128 + row) * 64 + c];
        *(uint32_t*)(smem + G1_A + (uint32_t)(row * 136 + c * 2) * 2) = v;
    }
    // fill B: h fp32 -> fp16
    for (int idx = tid; idx < 4096; idx += 256) {     // 128 rows x 32 float4
        int row = idx >> 5, c = idx & 31;
        float4 v = *(const float4*)&h[((size_t)row * SPN + sp) * FF + c * 4];
        uint32_t off = (uint32_t)(row * 136 + c * 4) * 2;
        *(uint32_t*)(smem + G1_B + off) = h2_u32(__floats2half2_rn(v.x, v.y));
        *(uint32_t*)(smem + G1_B + off + 4) = h2_u32(__floats2half2_rn(v.z, v.w));
    }
    __syncthreads();

    float acc[4][4][4];
#pragma unroll
    for (int i = 0; i < 4; i++)
#pragma unroll
        for (int j = 0; j < 4; j++)
#pragma unroll
            for (int q = 0; q < 4; q++) acc[i][j][q] = 0.f;

#pragma unroll
    for (int ks = 0; ks < 8; ks++) {
        int kb = ks * 16;
        uint32_t bh[4][2];
        int bko = kb + ((lane >> 3) & 1) * 8;
#pragma unroll
        for (int nt = 0; nt < 4; nt++) {
            uint32_t boff = (uint32_t)((wn * 32 + nt * 8 + (lane & 7)) * 136 + bko) * 2;
            ldsm2(bh[nt], sb + G1_B + boff);
        }
        int ako = kb + (lane >> 4) * 8;
#pragma unroll
        for (int mt = 0; mt < 4; mt++) {
            uint32_t aoff = (uint32_t)((wm * 64 + mt * 16 + (lane & 15)) * 136 + ako) * 2;
            uint32_t ah[4];
            ldsm4(ah, sb + G1_A + aoff);
#pragma unroll
            for (int nt = 0; nt < 4; nt++) mma16816(acc[mt][nt], ah, bh[nt]);
        }
    }

    // epilogue: fp16 single plane, half2 stores
#pragma unroll
    for (int mt = 0; mt < 4; mt++) {
#pragma unroll
        for (int nt = 0; nt < 4; nt++) {
            int gn0 = nb * 128 + wm * 64 + mt * 16 + (lane >> 2);
            int col = wn * 32 + nt * 8 + (lane & 3) * 2;
            *(__half2*)&g_gt[((size_t)sp * 512 + gn0) * 128 + col] =
                __floats2half2_rn(acc[mt][nt][0], acc[mt][nt][1]);
            *(__half2*)&g_gt[((size_t)sp * 512 + gn0 + 8) * 128 + col] =
                __floats2half2_rn(acc[mt][nt][2], acc[mt][nt][3]);
        }
    }
}

// ============================================================
// K5: fused softmax + AV GEMM, one CTA per sp, 512 threads (16 warps)
//     Phase 1: softmax; exact fp32 'a' -> out2, fp16 copy -> SMEM planes.
//     Phase 2: attn_res = 0.25 * sum_h a_h @ g_h^T, B double-buffered cp.async.
// ============================================================
#define G2_A     0                        // 4 planes x 128 x 136 halves
#define G2_PLANE 34816
#define G2_B0    139264
#define G2_B1    174080
#define G2_SIZE  208896

// B tile fill: 128 rows x 256B = 16 chunks of 16B per row, padded row stride 272B.
__device__ __forceinline__ void fill_b_tile(uint32_t dbuf, const __half* src, int tid) {
#pragma unroll
    for (int q = 0; q < 4; q++) {
        int idx = tid + q * 512;          // 0..2047
        int r = idx >> 4, c = idx & 15;   // r: 0..127 rows, c: 0..15 16B-chunks
        cpasync16(dbuf + (uint32_t)(r * 272 + c * 16), src + r * 128 + c * 8);
    }
    cpcommit();
}

__global__ void __launch_bounds__(512) k_g2(float* __restrict__ out1,
                                            float* __restrict__ out2) {
    extern __shared__ char smem[];
    uint32_t sb = smem_u32(smem);
    int tid = threadIdx.x;
    int lane = tid & 31, wid = tid >> 5;      // wid 0..15
    int wm = wid & 3, wn = wid >> 2;          // warp tile: 32(i) x 32(d)
    int sp = blockIdx.x;

    // prefetch head-0 B tile
    fill_b_tile(sb + G2_B0, g_gt + (size_t)sp * 65536, tid);

    // ---- Phase 1: softmax (warp per row, 8 rows per warp) ----
    {
        float4 slj[4];
#pragma unroll
        for (int u = 0; u < 4; u++)
            slj[u] = *(const float4*)&g_sl[(sp * 128 + lane + 32 * u) * 4];

        for (int it = 0; it < 8; it++) {
            int i = it * 16 + wid;
            float4 sri = *(const float4*)&g_sr[(sp * 128 + i) * 4];
            float e[4][4];
#pragma unroll
            for (int u = 0; u < 4; u++) {
                int j = lane + 32 * u;
                float v[4] = {sri.x + slj[u].x, sri.y + slj[u].y,
                              sri.z + slj[u].z, sri.w + slj[u].w};
#pragma unroll
                for (int hh = 0; hh < 4; hh++) {
                    float x = v[hh];
                    x = (x >= 0.f) ? x : 0.2f * x;
                    e[u][hh] = (j == i) ? -3.0e38f : x;
                }
            }
#pragma unroll
            for (int hh = 0; hh < 4; hh++) {
                float m = fmaxf(fmaxf(e[0][hh], e[1][hh]), fmaxf(e[2][hh], e[3][hh]));
                for (int o = 16; o; o >>= 1) m = fmaxf(m, __shfl_xor_sync(0xffffffffu, m, o));
                float s = 0.f;
#pragma unroll
                for (int u = 0; u < 4; u++) {
                    int j = lane + 32 * u;
                    float p = (j == i) ? 0.f : __expf(e[u][hh] - m);
                    e[u][hh] = p;
                    s += p;
                }
                for (int o = 16; o; o >>= 1) s += __shfl_xor_sync(0xffffffffu, s, o);
                float inv = 1.0f / s;
#pragma unroll
                for (int u = 0; u < 4; u++) e[u][hh] *= inv;
            }
            // exact fp32 'a' to output
            float* base = out2 + (size_t)sp * 65536 + (size_t)i * 512;
#pragma unroll
            for (int u = 0; u < 4; u++) {
                int j = lane + 32 * u;
                *(float4*)&base[j * 4] = make_float4(e[u][0], e[u][1], e[u][2], e[u][3]);
            }
            // fp16 copy into SMEM planes [h][i][j]
#pragma unroll
            for (int hh = 0; hh < 4; hh++) {
                uint32_t pb = G2_A + hh * G2_PLANE + (uint32_t)(i * 136) * 2;
#pragma unroll
                for (int u = 0; u < 4; u++) {
                    int j = lane + 32 * u;
                    *(__half*)(smem + pb + j * 2) = __float2half_rn(e[u][hh]);
                }
            }
        }
    }
    __syncthreads();

    // ---- Phase 2: AV MMA over 4 heads ----
    float acc[2][4][4];
#pragma unroll
    for (int i = 0; i < 2; i++)
#pragma unroll
        for (int j = 0; j < 4; j++)
#pragma unroll
            for (int q = 0; q < 4; q++) acc[i][j][q] = 0.f;

    for (int hh = 0; hh < 4; hh++) {
        if (hh < 3) {   // prefetch next head into other buffer
            uint32_t dbuf = ((hh + 1) & 1) ? G2_B1 : G2_B0;
            fill_b_tile(sb + dbuf, g_gt + (size_t)sp * 65536 + (hh + 1) * 128 * 128, tid);
            cpwait<1>();
        } else {
            cpwait<0>();
        }
        __syncthreads();

        uint32_t bbuf = (hh & 1) ? G2_B1 : G2_B0;
        uint32_t aplane = G2_A + hh * G2_PLANE;
#pragma unroll
        for (int ks = 0; ks < 8; ks++) {
            int kb = ks * 16;
            uint32_t bh[4][2];
            int bko = kb + ((lane >> 3) & 1) * 8;
#pragma unroll
            for (int nt = 0; nt < 4; nt++) {
                uint32_t boff = (uint32_t)((wn * 32 + nt * 8 + (lane & 7)) * 136 + bko) * 2;
                ldsm2(bh[nt], sb + bbuf + boff);
            }
            int ako = kb + (lane >> 4) * 8;
#pragma unroll
            for (int mt = 0; mt < 2; mt++) {
                uint32_t aoff = (uint32_t)((wm * 32 + mt * 16 + (lane & 15)) * 136 + ako) * 2;
                uint32_t af[4];
                ldsm4(af, sb + aplane + aoff);
#pragma unroll
                for (int nt = 0; nt < 4; nt++) mma16816(acc[mt][nt], af, bh[nt]);
            }
        }
        __syncthreads();   // all warps done with bbuf before it is refilled (hh+2)
    }

    // epilogue: x0.25, output layout (A, S, P, D)
#pragma unroll
    for (int mt = 0; mt < 2; mt++) {
#pragma unroll
        for (int nt = 0; nt < 4; nt++) {
            int i0 = wm * 32 + mt * 16 + (lane >> 2);
            int d0 = wn * 32 + nt * 8 + (lane & 3) * 2;
            float2 v0 = make_float2(acc[mt][nt][0] * 0.25f, acc[mt][nt][1] * 0.25f);
            float2 v1 = make_float2(acc[mt][nt][2] * 0.25f, acc[mt][nt][3] * 0.25f);
            *(float2*)&out1[((size_t)i0 * SPN + sp) * 128 + d0] = v0;
            *(float2*)&out1[((size_t)(i0 + 8) * SPN + sp) * 128 + d0] = v1;
        }
    }
}

// ============================================================
extern "C" void kernel_launch(void* const* d_in, const int* in_sizes, int n_in,
                              void* d_out, int out_size) {
    const float* h  = (const float*)d_in[0];
    const float* Wl = (const float*)d_in[1];
    const float* Wr = (const float*)d_in[2];
    const float* wa = (const float*)d_in[3];

    float* out1 = (float*)d_out;                 // attn_res: A*S*P*D
    float* out2 = out1 + (size_t)AA * SPN * DD;  // a: S*P*A*A*H

    // Unconditional (no static guards): immediate, idempotent, capture-safe.
    cudaFuncSetAttribute(k_g1, cudaFuncAttributeMaxDynamicSharedMemorySize, G1_SIZE);
    cudaFuncSetAttribute(k_g2, cudaFuncAttributeMaxDynamicSharedMemorySize, G2_SIZE);

    k_u<<<1, 512>>>(Wl, Wr, wa);
    k_s<<<RR / 8, 256>>>(h);
    k_split_w<<<(NNW * FF) / 256, 256>>>(Wr);
    k_g1<<<dim3(4, SPN), 256, G1_SIZE>>>(h);
    k_g2<<<SPN, 512, G2_SIZE>>>(out1, out2);
}